// round 2
// baseline (speedup 1.0000x reference)
#include <cuda_runtime.h>

// Problem constants (fixed by reference setup_inputs)
constexpr int N  = 100000;   // nodes
constexpr int E  = 3200000;  // edges
constexpr int FIN = 512;
constexpr int SCAN_BLOCKS = 98;  // ceil(N / 1024)

// ---------------- scratch (no mallocs allowed) ----------------
__device__ int   g_cnt[N];
__device__ int   g_bsum[128];
__device__ int   g_bbase[128];
__device__ int   g_rowptr[N + 1];
__device__ int   g_cur[N];
__device__ int   g_csrc[E];
__device__ float g_dinv[N];
__device__ float g_h1s[N * 16];   // h1 * dinv[row]
__device__ float g_h2s[N * 16];   // h2 * dinv[row]

// ---------------- helpers ----------------
__device__ __forceinline__ void ffma2(unsigned long long& d,
                                      unsigned long long a,
                                      unsigned long long b) {
    asm("fma.rn.f32x2 %0, %1, %2, %0;" : "+l"(d) : "l"(a), "l"(b));
}
__device__ __forceinline__ unsigned long long bcast2(float v) {
    unsigned long long r;
    asm("mov.b64 %0, {%1, %1};" : "=l"(r) : "f"(v));
    return r;
}
__device__ __forceinline__ float2 unpack2(unsigned long long v) {
    float2 r;
    asm("mov.b64 {%0, %1}, %2;" : "=f"(r.x), "=f"(r.y) : "l"(v));
    return r;
}

// ---------------- CSR build ----------------
__global__ void k_zero() {
    int i = blockIdx.x * blockDim.x + threadIdx.x;
    if (i < N) g_cnt[i] = 0;
}

__global__ void k_hist(const int* __restrict__ ei) {
    int i = blockIdx.x * blockDim.x + threadIdx.x;   // over E/4
    const int4* dst4 = reinterpret_cast<const int4*>(ei + E);
    int4 d = dst4[i];
    atomicAdd(&g_cnt[d.x], 1);
    atomicAdd(&g_cnt[d.y], 1);
    atomicAdd(&g_cnt[d.z], 1);
    atomicAdd(&g_cnt[d.w], 1);
}

__global__ void k_scan1() {
    __shared__ int sh[1024];
    int t = threadIdx.x;
    int i = blockIdx.x * 1024 + t;
    int v = (i < N) ? g_cnt[i] : 0;
    sh[t] = v;
    __syncthreads();
    for (int o = 512; o > 0; o >>= 1) {
        if (t < o) sh[t] += sh[t + o];
        __syncthreads();
    }
    if (t == 0) g_bsum[blockIdx.x] = sh[0];
}

__global__ void k_scan2() {
    __shared__ int sh[128];
    int t = threadIdx.x;
    int v = (t < SCAN_BLOCKS) ? g_bsum[t] : 0;
    sh[t] = v;
    __syncthreads();
    for (int o = 1; o < 128; o <<= 1) {
        int a = (t >= o) ? sh[t - o] : 0;
        __syncthreads();
        sh[t] += a;
        __syncthreads();
    }
    if (t < SCAN_BLOCKS) g_bbase[t] = sh[t] - v;   // exclusive
    if (t == 127) g_rowptr[N] = sh[127];           // total == E
}

__global__ void k_scan3() {
    __shared__ int sh[1024];
    int t = threadIdx.x;
    int i = blockIdx.x * 1024 + t;
    int v = (i < N) ? g_cnt[i] : 0;
    sh[t] = v;
    __syncthreads();
    for (int o = 1; o < 1024; o <<= 1) {
        int a = (t >= o) ? sh[t - o] : 0;
        __syncthreads();
        sh[t] += a;
        __syncthreads();
    }
    if (i < N) {
        int excl = sh[t] - v + g_bbase[blockIdx.x];
        g_rowptr[i] = excl;
        g_cur[i]    = excl;
        g_dinv[i]   = rsqrtf((float)(v + 1));   // +1 self-loop
    }
}

__global__ void k_scatter(const int* __restrict__ ei) {
    int e = blockIdx.x * blockDim.x + threadIdx.x;  // exact E threads
    int s = ei[e];
    int d = ei[E + e];
    int pos = atomicAdd(&g_cur[d], 1);
    g_csrc[pos] = s;
}

// ---------------- GEMM1: h1s = (x @ W1) * dinv[row] ----------------
// 256 threads = 256 rows per block; W1 (512x16) resident in smem;
// x staged per 32-k tile transposed in smem; packed f32x2 FMAs.
__global__ void k_gemm1(const float* __restrict__ x,
                        const float* __restrict__ W1) {
    extern __shared__ float sm[];
    float* ws = sm;            // 8192 floats (512x16)
    float* xs = sm + 8192;     // 32 x 257 floats (k-major, padded)

    const int t = threadIdx.x;
    const int row0 = blockIdx.x * 256;
    const int row = row0 + t;

    // load W1 into smem (coalesced float4)
    {
        const float4* w4 = reinterpret_cast<const float4*>(W1);
        float4* s4 = reinterpret_cast<float4*>(ws);
#pragma unroll
        for (int i = 0; i < 8; ++i) s4[i * 256 + t] = w4[i * 256 + t];
    }

    unsigned long long a[8];
#pragma unroll
    for (int j = 0; j < 8; ++j) a[j] = 0ULL;

    for (int kt = 0; kt < 16; ++kt) {
        __syncthreads();
        // stage x tile: rows [row0,row0+256), k [kt*32, kt*32+32)
#pragma unroll
        for (int i = 0; i < 8; ++i) {
            int fid = i * 256 + t;
            int r = fid >> 3;
            int j = fid & 7;
            int gr = row0 + r;
            if (gr >= N) gr = N - 1;   // clamp (results discarded by store guard)
            float4 xv = *reinterpret_cast<const float4*>(
                x + (size_t)gr * FIN + kt * 32 + j * 4);
            int kk = j * 4;
            xs[(kk + 0) * 257 + r] = xv.x;
            xs[(kk + 1) * 257 + r] = xv.y;
            xs[(kk + 2) * 257 + r] = xv.z;
            xs[(kk + 3) * 257 + r] = xv.w;
        }
        __syncthreads();

#pragma unroll
        for (int kk = 0; kk < 32; ++kk) {
            float xv = xs[kk * 257 + t];
            unsigned long long xx = bcast2(xv);
            const longlong2* wr = reinterpret_cast<const longlong2*>(
                ws + (kt * 32 + kk) * 16);
            longlong2 p0 = wr[0];
            longlong2 p1 = wr[1];
            longlong2 p2 = wr[2];
            longlong2 p3 = wr[3];
            ffma2(a[0], xx, (unsigned long long)p0.x);
            ffma2(a[1], xx, (unsigned long long)p0.y);
            ffma2(a[2], xx, (unsigned long long)p1.x);
            ffma2(a[3], xx, (unsigned long long)p1.y);
            ffma2(a[4], xx, (unsigned long long)p2.x);
            ffma2(a[5], xx, (unsigned long long)p2.y);
            ffma2(a[6], xx, (unsigned long long)p3.x);
            ffma2(a[7], xx, (unsigned long long)p3.y);
        }
    }

    if (row < N) {
        float dv = g_dinv[row];
        float* dst = g_h1s + (size_t)row * 16;
        float4* d4 = reinterpret_cast<float4*>(dst);
#pragma unroll
        for (int q = 0; q < 4; ++q) {
            float2 lo = unpack2(a[2 * q]);
            float2 hi = unpack2(a[2 * q + 1]);
            float4 o;
            o.x = lo.x * dv; o.y = lo.y * dv;
            o.z = hi.x * dv; o.w = hi.y * dv;
            d4[q] = o;
        }
    }
}

// ---------------- agg1 + bias + relu + (h @ W2) fused ----------------
// one warp per node: lanes = 2 edge slots x 16 cols
__global__ void k_agg1(const float* __restrict__ b1,
                       const float* __restrict__ W2) {
    int warp = (blockIdx.x * blockDim.x + threadIdx.x) >> 5;
    if (warp >= N) return;
    int lane = threadIdx.x & 31;
    int half = lane >> 4;
    int col = lane & 15;

    int start = g_rowptr[warp];
    int end   = g_rowptr[warp + 1];

    float acc = 0.f;
    for (int base = start; base < end; base += 32) {
        int e = base + lane;
        int s = (e < end) ? g_csrc[e] : 0;
        int m = end - base;
#pragma unroll
        for (int j = 0; j < 32; j += 2) {
            int jj = j + half;
            int sj = __shfl_sync(0xffffffffu, s, jj);
            if (jj < m) acc += g_h1s[(size_t)sj * 16 + col];
        }
    }
    acc += __shfl_xor_sync(0xffffffffu, acc, 16);   // all lanes: full edge sum

    float dv = g_dinv[warp];
    float selfv = g_h1s[(size_t)warp * 16 + col];
    float val = (acc + selfv) * dv + b1[col];
    float r = fmaxf(val, 0.f);

    // layer 2: h2[col] = sum_k r_k * W2[k][col]
    float h2 = 0.f;
#pragma unroll
    for (int k = 0; k < 16; ++k) {
        float rk = __shfl_sync(0xffffffffu, r, k, 16);
        h2 = fmaf(rk, W2[k * 16 + col], h2);
    }
    if (lane < 16) g_h2s[(size_t)warp * 16 + col] = h2 * dv;
}

// ---------------- agg2 + bias + log_softmax ----------------
__global__ void k_agg2(const float* __restrict__ b2,
                       float* __restrict__ out) {
    int warp = (blockIdx.x * blockDim.x + threadIdx.x) >> 5;
    if (warp >= N) return;
    int lane = threadIdx.x & 31;
    int half = lane >> 4;
    int col = lane & 15;

    int start = g_rowptr[warp];
    int end   = g_rowptr[warp + 1];

    float acc = 0.f;
    for (int base = start; base < end; base += 32) {
        int e = base + lane;
        int s = (e < end) ? g_csrc[e] : 0;
        int m = end - base;
#pragma unroll
        for (int j = 0; j < 32; j += 2) {
            int jj = j + half;
            int sj = __shfl_sync(0xffffffffu, s, jj);
            if (jj < m) acc += g_h2s[(size_t)sj * 16 + col];
        }
    }
    acc += __shfl_xor_sync(0xffffffffu, acc, 16);

    float dv = g_dinv[warp];
    float selfv = g_h2s[(size_t)warp * 16 + col];
    float val = (acc + selfv) * dv + b2[col];

    // log_softmax over the 16 cols (butterfly within each 16-lane half)
    float mx = val;
#pragma unroll
    for (int o = 8; o > 0; o >>= 1)
        mx = fmaxf(mx, __shfl_xor_sync(0xffffffffu, mx, o));
    float ex = __expf(val - mx);
    float sum = ex;
#pragma unroll
    for (int o = 8; o > 0; o >>= 1)
        sum += __shfl_xor_sync(0xffffffffu, sum, o);
    float res = val - mx - __logf(sum);

    if (lane < 16) out[(size_t)warp * 16 + col] = res;
}

// ---------------- launch ----------------
extern "C" void kernel_launch(void* const* d_in, const int* in_sizes, int n_in,
                              void* d_out, int out_size) {
    const float* x  = (const float*)d_in[0];
    const float* W1 = (const float*)d_in[1];
    const float* b1 = (const float*)d_in[2];
    const float* W2 = (const float*)d_in[3];
    const float* b2 = (const float*)d_in[4];
    const int*   ei = (const int*)d_in[5];
    float* out = (float*)d_out;

    const int smem = (8192 + 32 * 257) * (int)sizeof(float);  // 65664 B
    cudaFuncSetAttribute((const void*)k_gemm1,
                         cudaFuncAttributeMaxDynamicSharedMemorySize, smem);

    k_zero   <<<(N + 255) / 256, 256>>>();
    k_hist   <<<E / 4 / 256, 256>>>(ei);
    k_scan1  <<<SCAN_BLOCKS, 1024>>>();
    k_scan2  <<<1, 128>>>();
    k_scan3  <<<SCAN_BLOCKS, 1024>>>();
    k_scatter<<<E / 256, 256>>>(ei);
    k_gemm1  <<<(N + 255) / 256, 256, smem>>>(x, W1);
    k_agg1   <<<(N * 32 + 255) / 256 / 1, 256>>>(b1, W2);
    k_agg2   <<<(N * 32) / 256, 256>>>(b2, out);
}